// round 3
// baseline (speedup 1.0000x reference)
#include <cuda_runtime.h>

// Problem constants
#define BB 256   // batch
#define TT 256   // time
#define DD 64    // input dim
#define HH 256   // hidden
#define GG 768   // 3*H gates

typedef unsigned long long ull;

// ---------------- scratch (static device memory; no allocations) ----------------
__device__ float  g_XT[TT * BB * DD];              //  16.8 MB  x transposed to (t,b,d)
__device__ float  g_H1[TT * BB * 2 * HH];          // 134.2 MB  layer-0 output (t,b,512)
__device__ float  g_GI[2 * TT * BB * GG];          // 402.7 MB  gi for both dirs (reused per layer)
__device__ float4 g_WV0[2 * 3 * 64 * 256];         // layer-0 w_hh, k-major lane-coalesced
__device__ float4 g_WV1[2 * 3 * 64 * 256];         // layer-1 w_hh

// ---------------- helpers ----------------
__device__ __forceinline__ void fma2(ull &d, ull a, ull b) {
    // packed 2xfp32 FMA (sm_100+): d = a*b + d, lanewise
    asm volatile("fma.rn.f32x2 %0, %1, %2, %0;" : "+l"(d) : "l"(a), "l"(b));
}
__device__ __forceinline__ float hadd2(ull a) {
    float lo, hi;
    asm volatile("mov.b64 {%0, %1}, %2;" : "=f"(lo), "=f"(hi) : "l"(a));
    return lo + hi;
}
__device__ __forceinline__ float sigmoidf_fast(float x) {
    return 1.0f / (1.0f + __expf(-x));
}
__device__ __forceinline__ unsigned cvt_tf32(float f) {
    unsigned r;
    asm volatile("cvt.rna.tf32.f32 %0, %1;" : "=r"(r) : "f"(f));
    return r;
}

// ---------------- 1) transpose x: (B,T,D) -> (T,B,D) ----------------
__global__ void transpose_x(const float* __restrict__ x) {
    int i = blockIdx.x * blockDim.x + threadIdx.x;      // B*T*16 float4s
    if (i >= BB * TT * (DD / 4)) return;
    int d4 = i & 15;
    int t  = (i >> 4) & 255;
    int b  = i >> 12;
    const float4* src = reinterpret_cast<const float4*>(x);
    float4* dst = reinterpret_cast<float4*>(g_XT);
    dst[((t * BB + b) * (DD / 4)) + d4] = src[((b * TT + t) * (DD / 4)) + d4];
}

// ---------------- 2) shuffle w_hh to [d][gate][k4][j] float4 (k-major, j coalesced) ----------------
__global__ void prep_whh(int layer, const float* __restrict__ w) {
    int i = blockIdx.x * blockDim.x + threadIdx.x;      // 2*3*64*256 = 98304
    if (i >= 2 * 3 * 64 * 256) return;
    int j  = i & 255;
    int k4 = (i >> 8) & 63;
    int dg = i >> 14;            // d*3 + g  (0..5)
    int d  = dg / 3;
    int g  = dg % 3;
    // w layout: [d][row=g*256+j][k], k fastest
    const float* src = w + ((size_t)(d * GG + g * 256 + j)) * HH + k4 * 4;
    float4 v = make_float4(src[0], src[1], src[2], src[3]);
    float4* dst = layer ? g_WV1 : g_WV0;
    dst[i] = v;
}

// ---------------- 3) gi GEMM: C[d][m][g] = A[m][:] . W[d][g][:] + bias ----------------
// A row-major (M x K), W row-major (768 x K) per dir, tf32x3 split-precision mma,
// 128x128 tiles. Each operand f = hi + lo (hi = cvt.rna.tf32(f), lo = f - hi);
// acc += hi*hi + hi*lo + lo*hi  -> ~fp32 accuracy (lo*lo term ~2^-22, dropped).
// bias = b_ih[g] + (g < 2H ? b_hh[g] : 0)   (b_hh_n is applied inside r*(...) in the scan)
#define Bb_M 128
#define Bb_N 128
#define Bb_K 16
#define SSTR 20   // smem row stride in floats (pad kills 4-way conflicts)

__device__ __forceinline__ void mma_tf32(float* acc, const unsigned* a, unsigned b0, unsigned b1) {
    asm volatile(
        "mma.sync.aligned.m16n8k8.row.col.f32.tf32.tf32.f32 "
        "{%0,%1,%2,%3}, {%4,%5,%6,%7}, {%8,%9}, {%0,%1,%2,%3};\n"
        : "+f"(acc[0]), "+f"(acc[1]), "+f"(acc[2]), "+f"(acc[3])
        : "r"(a[0]), "r"(a[1]), "r"(a[2]), "r"(a[3]), "r"(b0), "r"(b1));
}

__global__ void __launch_bounds__(256) gemm_tf32(int layer,
                                                 const float* __restrict__ Wih,
                                                 const float* __restrict__ bih,
                                                 const float* __restrict__ bhh) {
    __shared__ float sA[2][Bb_M * SSTR];
    __shared__ float sB[2][Bb_N * SSTR];

    const float* A = layer ? g_H1 : g_XT;
    const int K    = layer ? 512 : 64;
    float* C = g_GI;

    int tid  = threadIdx.x;
    int m0   = blockIdx.x * Bb_M;
    int n0   = blockIdx.y * Bb_N;
    int d    = blockIdx.z;
    const float* Ab = A + (size_t)m0 * K;
    const float* Wb = Wih + ((size_t)d * GG + n0) * K;
    float* Cb = C + (size_t)d * (TT * BB) * GG;

    int lane = tid & 31, wid = tid >> 5;
    int wm = wid & 3, wn = wid >> 2;   // 4 x 2 warp grid, warp tile 32(m) x 64(n)

    float acc[2][8][4];
#pragma unroll
    for (int a = 0; a < 2; a++)
#pragma unroll
        for (int b = 0; b < 8; b++)
#pragma unroll
            for (int c = 0; c < 4; c++) acc[a][b][c] = 0.0f;

    auto load_tile = [&](int kt, int buf) {
        int k0 = kt * Bb_K;
#pragma unroll
        for (int i = 0; i < 2; i++) {
            int s   = tid * 2 + i;        // 0..511
            int row = s >> 2;
            int seg = s & 3;
            unsigned da = (unsigned)__cvta_generic_to_shared(&sA[buf][row * SSTR + seg * 4]);
            const float* ga = Ab + (size_t)row * K + k0 + seg * 4;
            asm volatile("cp.async.cg.shared.global [%0], [%1], 16;\n" :: "r"(da), "l"(ga));
            unsigned db = (unsigned)__cvta_generic_to_shared(&sB[buf][row * SSTR + seg * 4]);
            const float* gb = Wb + (size_t)row * K + k0 + seg * 4;
            asm volatile("cp.async.cg.shared.global [%0], [%1], 16;\n" :: "r"(db), "l"(gb));
        }
        asm volatile("cp.async.commit_group;\n" ::: "memory");
    };

    const int KT = K / Bb_K;
    load_tile(0, 0);
    for (int kt = 0; kt < KT; kt++) {
        int buf = kt & 1;
        if (kt + 1 < KT) {
            load_tile(kt + 1, buf ^ 1);
            asm volatile("cp.async.wait_group 1;\n" ::: "memory");
        } else {
            asm volatile("cp.async.wait_group 0;\n" ::: "memory");
        }
        __syncthreads();
        const float* a_s = sA[buf];
        const float* b_s = sB[buf];
#pragma unroll
        for (int ks = 0; ks < 2; ks++) {
            int kk = ks * 8;
            unsigned ahi[2][4], alo[2][4];
#pragma unroll
            for (int mf = 0; mf < 2; mf++) {
                const float* p = a_s + (wm * 32 + mf * 16 + (lane >> 2)) * SSTR + kk + (lane & 3);
                float f0 = p[0];
                float f1 = p[8 * SSTR];
                float f2 = p[4];
                float f3 = p[8 * SSTR + 4];
                ahi[mf][0] = cvt_tf32(f0); alo[mf][0] = __float_as_uint(f0 - __uint_as_float(ahi[mf][0]));
                ahi[mf][1] = cvt_tf32(f1); alo[mf][1] = __float_as_uint(f1 - __uint_as_float(ahi[mf][1]));
                ahi[mf][2] = cvt_tf32(f2); alo[mf][2] = __float_as_uint(f2 - __uint_as_float(ahi[mf][2]));
                ahi[mf][3] = cvt_tf32(f3); alo[mf][3] = __float_as_uint(f3 - __uint_as_float(ahi[mf][3]));
            }
#pragma unroll
            for (int nf = 0; nf < 8; nf++) {
                const float* p = b_s + (wn * 64 + nf * 8 + (lane >> 2)) * SSTR + kk + (lane & 3);
                float g0 = p[0];
                float g1 = p[4];
                unsigned bhi0 = cvt_tf32(g0), blo0 = __float_as_uint(g0 - __uint_as_float(bhi0));
                unsigned bhi1 = cvt_tf32(g1), blo1 = __float_as_uint(g1 - __uint_as_float(bhi1));
#pragma unroll
                for (int mf = 0; mf < 2; mf++) {
                    mma_tf32(acc[mf][nf], ahi[mf], bhi0, bhi1);   // hi * hi
                    mma_tf32(acc[mf][nf], ahi[mf], blo0, blo1);   // hi * lo
                    mma_tf32(acc[mf][nf], alo[mf], bhi0, bhi1);   // lo * hi
                }
            }
        }
        __syncthreads();
    }

    // epilogue: c0:(r,c) c1:(r,c+1) c2:(r+8,c) c3:(r+8,c+1), c = (lane&3)*2
#pragma unroll
    for (int mf = 0; mf < 2; mf++)
#pragma unroll
        for (int nf = 0; nf < 8; nf++)
#pragma unroll
            for (int i = 0; i < 4; i++) {
                int row = m0 + wm * 32 + mf * 16 + (lane >> 2) + ((i >> 1) ? 8 : 0);
                int col = n0 + wn * 64 + nf * 8 + (lane & 3) * 2 + (i & 1);
                float bias = __ldg(&bih[d * GG + col]) +
                             (col < 2 * HH ? __ldg(&bhh[d * GG + col]) : 0.0f);
                Cb[(size_t)row * GG + col] = acc[mf][nf][i] + bias;
            }
}

// ---------------- 4) GRU scan ----------------
// Block: 4 batch rows x full hidden. grid = (64 batch-chunks, 2 dirs).
// Thread j owns gate rows {j, 256+j, 512+j} (r_j, z_j, n_j) -> updates h[cb][j].
// Weights streamed from L2 in lane-coalesced float4 layout; h held in smem (broadcast reads).
__global__ void __launch_bounds__(256, 1) gru_scan(int layer,
                                                   const float* __restrict__ bhh,
                                                   float* __restrict__ fin) {
    __shared__ ulonglong2 hs[4][64];          // [cb][k4]; each elem = 4 packed floats
    float* hsf = reinterpret_cast<float*>(hs);  // hsf[cb*256 + j]

    int tid = threadIdx.x;            // j
    int d   = blockIdx.y;
    int b0  = blockIdx.x * 4;

    const ulonglong2* WV =
        reinterpret_cast<const ulonglong2*>(layer ? g_WV1 : g_WV0) + (size_t)d * 3 * 64 * 256;

    // zero h
    hs[tid >> 6][tid & 63] = make_ulonglong2(0ull, 0ull);
    float bn = __ldg(&bhh[d * GG + 2 * HH + tid]);   // b_hh_n[j] (inside r*(...))
    __syncthreads();

    float hnew[4] = {0.f, 0.f, 0.f, 0.f};

    for (int s = 0; s < TT; s++) {
        int t = d ? (TT - 1 - s) : s;
        const float* gip = g_GI + ((size_t)d * (TT * BB) + (size_t)t * BB + b0) * GG;

        float gr[4], gz[4], gn[4];
#pragma unroll
        for (int cb = 0; cb < 4; cb++) {
            gr[cb] = __ldg(gip + cb * GG + tid);
            gz[cb] = __ldg(gip + cb * GG + 256 + tid);
            gn[cb] = __ldg(gip + cb * GG + 512 + tid);
        }

        ull ar[4] = {0, 0, 0, 0}, az[4] = {0, 0, 0, 0}, an[4] = {0, 0, 0, 0};

#pragma unroll 4
        for (int k4 = 0; k4 < 64; k4++) {
            ulonglong2 h0 = hs[0][k4];
            ulonglong2 h1 = hs[1][k4];
            ulonglong2 h2 = hs[2][k4];
            ulonglong2 h3 = hs[3][k4];
            ulonglong2 wr = WV[(0 * 64 + k4) * 256 + tid];
            ulonglong2 wz = WV[(1 * 64 + k4) * 256 + tid];
            ulonglong2 wn = WV[(2 * 64 + k4) * 256 + tid];

            fma2(ar[0], h0.x, wr.x); fma2(ar[0], h0.y, wr.y);
            fma2(ar[1], h1.x, wr.x); fma2(ar[1], h1.y, wr.y);
            fma2(ar[2], h2.x, wr.x); fma2(ar[2], h2.y, wr.y);
            fma2(ar[3], h3.x, wr.x); fma2(ar[3], h3.y, wr.y);

            fma2(az[0], h0.x, wz.x); fma2(az[0], h0.y, wz.y);
            fma2(az[1], h1.x, wz.x); fma2(az[1], h1.y, wz.y);
            fma2(az[2], h2.x, wz.x); fma2(az[2], h2.y, wz.y);
            fma2(az[3], h3.x, wz.x); fma2(az[3], h3.y, wz.y);

            fma2(an[0], h0.x, wn.x); fma2(an[0], h0.y, wn.y);
            fma2(an[1], h1.x, wn.x); fma2(an[1], h1.y, wn.y);
            fma2(an[2], h2.x, wn.x); fma2(an[2], h2.y, wn.y);
            fma2(an[3], h3.x, wn.x); fma2(an[3], h3.y, wn.y);
        }

#pragma unroll
        for (int cb = 0; cb < 4; cb++) {
            float ghr = hadd2(ar[cb]);
            float ghz = hadd2(az[cb]);
            float ghn = hadd2(an[cb]);
            float r = sigmoidf_fast(gr[cb] + ghr);
            float z = sigmoidf_fast(gz[cb] + ghz);
            float n = tanhf(gn[cb] + r * (ghn + bn));
            float hold = hsf[cb * 256 + tid];
            hnew[cb] = n + z * (hold - n);
        }
        __syncthreads();
#pragma unroll
        for (int cb = 0; cb < 4; cb++) hsf[cb * 256 + tid] = hnew[cb];
        __syncthreads();

        if (layer == 0) {
            float* hp = g_H1 + ((size_t)t * BB + b0) * (2 * HH) + (d ? HH : 0) + tid;
#pragma unroll
            for (int cb = 0; cb < 4; cb++) hp[cb * 2 * HH] = hnew[cb];
        }
    }

    if (layer != 0) {
#pragma unroll
        for (int cb = 0; cb < 4; cb++)
            fin[(size_t)(b0 + cb) * (2 * HH) + (d ? HH : 0) + tid] = hnew[cb];
    }
}

// ---------------- launch ----------------
extern "C" void kernel_launch(void* const* d_in, const int* in_sizes, int n_in,
                              void* d_out, int out_size) {
    (void)in_sizes; (void)n_in; (void)out_size;
    const float* x     = (const float*)d_in[0];
    const float* w_ih0 = (const float*)d_in[1];
    const float* w_hh0 = (const float*)d_in[2];
    const float* b_ih0 = (const float*)d_in[3];
    const float* b_hh0 = (const float*)d_in[4];
    const float* w_ih1 = (const float*)d_in[5];
    const float* w_hh1 = (const float*)d_in[6];
    const float* b_ih1 = (const float*)d_in[7];
    const float* b_hh1 = (const float*)d_in[8];
    float* out = (float*)d_out;

    transpose_x<<<(BB * TT * (DD / 4) + 255) / 256, 256>>>(x);
    prep_whh<<<(2 * 3 * 64 * 256 + 255) / 256, 256>>>(0, w_hh0);
    prep_whh<<<(2 * 3 * 64 * 256 + 255) / 256, 256>>>(1, w_hh1);

    dim3 gg(512, 6, 2);   // M/128, 768/128, dirs
    gemm_tf32<<<gg, 256>>>(0, w_ih0, b_ih0, b_hh0);
    gru_scan<<<dim3(64, 2, 1), 256>>>(0, b_hh0, nullptr);
    gemm_tf32<<<gg, 256>>>(1, w_ih1, b_ih1, b_hh1);
    gru_scan<<<dim3(64, 2, 1), 256>>>(1, b_hh1, out);
}

// round 5
// speedup vs baseline: 1.0038x; 1.0038x over previous
#include <cuda_runtime.h>
#include <cstdint>

// Problem constants
#define BB 256   // batch
#define TT 256   // time
#define DD 64    // input dim
#define HH 256   // hidden
#define GG 768   // 3*H gates

typedef unsigned long long ull;

// ---------------- scratch (static device memory; no allocations) ----------------
__device__ float  g_XT[TT * BB * DD];              //  16.8 MB  x transposed to (t,b,d)
__device__ float  g_H1[TT * BB * 2 * HH];          // 134.2 MB  layer-0 output (t,b,512)
__device__ float  g_GI[2 * TT * BB * GG];          // 402.7 MB  gi for both dirs (reused per layer)
__device__ float4 g_WV0[2 * 4 * 3 * 64 * 64];      // layer-0 w_hh  [d][rank][g][k4][jloc] float4
__device__ float4 g_WV1[2 * 4 * 3 * 64 * 64];      // layer-1 w_hh

// ---------------- helpers ----------------
__device__ __forceinline__ void fma2(ull &d, ull a, ull b) {
    asm volatile("fma.rn.f32x2 %0, %1, %2, %0;" : "+l"(d) : "l"(a), "l"(b));
}
__device__ __forceinline__ float hadd2(ull a) {
    float lo, hi;
    asm volatile("mov.b64 {%0, %1}, %2;" : "=f"(lo), "=f"(hi) : "l"(a));
    return lo + hi;
}
__device__ __forceinline__ float sigmoidf_fast(float x) {
    return 1.0f / (1.0f + __expf(-x));
}
__device__ __forceinline__ unsigned cvt_tf32(float f) {
    unsigned r;
    asm volatile("cvt.rna.tf32.f32 %0, %1;" : "=r"(r) : "f"(f));
    return r;
}
__device__ __forceinline__ unsigned mapa_sh(unsigned addr, unsigned rnk) {
    unsigned ra;
    asm volatile("mapa.shared::cluster.u32 %0, %1, %2;" : "=r"(ra) : "r"(addr), "r"(rnk));
    return ra;
}
#define CLUSTER_SYNC_() \
    asm volatile("barrier.cluster.arrive.aligned;\n\tbarrier.cluster.wait.aligned;" ::: "memory")

// ---------------- 1) transpose x: (B,T,D) -> (T,B,D) ----------------
__global__ void transpose_x(const float* __restrict__ x) {
    int i = blockIdx.x * blockDim.x + threadIdx.x;      // B*T*16 float4s
    if (i >= BB * TT * (DD / 4)) return;
    int d4 = i & 15;
    int t  = (i >> 4) & 255;
    int b  = i >> 12;
    const float4* src = reinterpret_cast<const float4*>(x);
    float4* dst = reinterpret_cast<float4*>(g_XT);
    dst[((t * BB + b) * (DD / 4)) + d4] = src[((b * TT + t) * (DD / 4)) + d4];
}

// ---------------- 2) shuffle w_hh to [d][rank][g][k4][jloc] float4 ----------------
// rank owns global j slice [rank*64, rank*64+64); value = w[d][g*256 + rank*64 + jloc][k4*4..+3]
__global__ void prep_whh(int layer, const float* __restrict__ w) {
    int i = blockIdx.x * blockDim.x + threadIdx.x;      // 2*4*3*64*64 = 98304
    if (i >= 2 * 4 * 3 * 64 * 64) return;
    int jloc = i & 63;
    int k4   = (i >> 6) & 63;
    int rest = i >> 12;          // 0..23 = (d*4 + r)*3 + g
    int g    = rest % 3;
    int dr   = rest / 3;
    int r    = dr & 3;
    int d    = dr >> 2;
    const float* src = w + ((size_t)(d * GG + g * 256 + r * 64 + jloc)) * HH + k4 * 4;
    float4 v = make_float4(src[0], src[1], src[2], src[3]);
    float4* dst = layer ? g_WV1 : g_WV0;
    dst[i] = v;
}

// ---------------- 3) gi GEMM: tf32x3 split-precision, 128x128 tiles ----------------
#define Bb_M 128
#define Bb_N 128
#define Bb_K 16
#define SSTR 20

__device__ __forceinline__ void mma_tf32(float* acc, const unsigned* a, unsigned b0, unsigned b1) {
    asm volatile(
        "mma.sync.aligned.m16n8k8.row.col.f32.tf32.tf32.f32 "
        "{%0,%1,%2,%3}, {%4,%5,%6,%7}, {%8,%9}, {%0,%1,%2,%3};\n"
        : "+f"(acc[0]), "+f"(acc[1]), "+f"(acc[2]), "+f"(acc[3])
        : "r"(a[0]), "r"(a[1]), "r"(a[2]), "r"(a[3]), "r"(b0), "r"(b1));
}

__global__ void __launch_bounds__(256) gemm_tf32(int layer,
                                                 const float* __restrict__ Wih,
                                                 const float* __restrict__ bih,
                                                 const float* __restrict__ bhh) {
    __shared__ float sA[2][Bb_M * SSTR];
    __shared__ float sB[2][Bb_N * SSTR];

    const float* A = layer ? g_H1 : g_XT;
    const int K    = layer ? 512 : 64;
    float* C = g_GI;

    int tid  = threadIdx.x;
    int m0   = blockIdx.x * Bb_M;
    int n0   = blockIdx.y * Bb_N;
    int d    = blockIdx.z;
    const float* Ab = A + (size_t)m0 * K;
    const float* Wb = Wih + ((size_t)d * GG + n0) * K;
    float* Cb = C + (size_t)d * (TT * BB) * GG;

    int lane = tid & 31, wid = tid >> 5;
    int wm = wid & 3, wn = wid >> 2;   // 4 x 2 warp grid, warp tile 32(m) x 64(n)

    float acc[2][8][4];
#pragma unroll
    for (int a = 0; a < 2; a++)
#pragma unroll
        for (int b = 0; b < 8; b++)
#pragma unroll
            for (int c = 0; c < 4; c++) acc[a][b][c] = 0.0f;

    auto load_tile = [&](int kt, int buf) {
        int k0 = kt * Bb_K;
#pragma unroll
        for (int i = 0; i < 2; i++) {
            int s   = tid * 2 + i;        // 0..511
            int row = s >> 2;
            int seg = s & 3;
            unsigned da = (unsigned)__cvta_generic_to_shared(&sA[buf][row * SSTR + seg * 4]);
            const float* ga = Ab + (size_t)row * K + k0 + seg * 4;
            asm volatile("cp.async.cg.shared.global [%0], [%1], 16;\n" :: "r"(da), "l"(ga));
            unsigned db = (unsigned)__cvta_generic_to_shared(&sB[buf][row * SSTR + seg * 4]);
            const float* gb = Wb + (size_t)row * K + k0 + seg * 4;
            asm volatile("cp.async.cg.shared.global [%0], [%1], 16;\n" :: "r"(db), "l"(gb));
        }
        asm volatile("cp.async.commit_group;\n" ::: "memory");
    };

    const int KT = K / Bb_K;
    load_tile(0, 0);
    for (int kt = 0; kt < KT; kt++) {
        int buf = kt & 1;
        if (kt + 1 < KT) {
            load_tile(kt + 1, buf ^ 1);
            asm volatile("cp.async.wait_group 1;\n" ::: "memory");
        } else {
            asm volatile("cp.async.wait_group 0;\n" ::: "memory");
        }
        __syncthreads();
        const float* a_s = sA[buf];
        const float* b_s = sB[buf];
#pragma unroll
        for (int ks = 0; ks < 2; ks++) {
            int kk = ks * 8;
            unsigned ahi[2][4], alo[2][4];
#pragma unroll
            for (int mf = 0; mf < 2; mf++) {
                const float* p = a_s + (wm * 32 + mf * 16 + (lane >> 2)) * SSTR + kk + (lane & 3);
                float f0 = p[0];
                float f1 = p[8 * SSTR];
                float f2 = p[4];
                float f3 = p[8 * SSTR + 4];
                ahi[mf][0] = cvt_tf32(f0); alo[mf][0] = __float_as_uint(f0 - __uint_as_float(ahi[mf][0]));
                ahi[mf][1] = cvt_tf32(f1); alo[mf][1] = __float_as_uint(f1 - __uint_as_float(ahi[mf][1]));
                ahi[mf][2] = cvt_tf32(f2); alo[mf][2] = __float_as_uint(f2 - __uint_as_float(ahi[mf][2]));
                ahi[mf][3] = cvt_tf32(f3); alo[mf][3] = __float_as_uint(f3 - __uint_as_float(ahi[mf][3]));
            }
#pragma unroll
            for (int nf = 0; nf < 8; nf++) {
                const float* p = b_s + (wn * 64 + nf * 8 + (lane >> 2)) * SSTR + kk + (lane & 3);
                float g0 = p[0];
                float g1 = p[4];
                unsigned bhi0 = cvt_tf32(g0), blo0 = __float_as_uint(g0 - __uint_as_float(bhi0));
                unsigned bhi1 = cvt_tf32(g1), blo1 = __float_as_uint(g1 - __uint_as_float(bhi1));
#pragma unroll
                for (int mf = 0; mf < 2; mf++) {
                    mma_tf32(acc[mf][nf], ahi[mf], bhi0, bhi1);   // hi * hi
                    mma_tf32(acc[mf][nf], ahi[mf], blo0, blo1);   // hi * lo
                    mma_tf32(acc[mf][nf], alo[mf], bhi0, bhi1);   // lo * hi
                }
            }
        }
        __syncthreads();
    }

#pragma unroll
    for (int mf = 0; mf < 2; mf++)
#pragma unroll
        for (int nf = 0; nf < 8; nf++)
#pragma unroll
            for (int i = 0; i < 4; i++) {
                int row = m0 + wm * 32 + mf * 16 + (lane >> 2) + ((i >> 1) ? 8 : 0);
                int col = n0 + wn * 64 + nf * 8 + (lane & 3) * 2 + (i & 1);
                float bias = __ldg(&bih[d * GG + col]) +
                             (col < 2 * HH ? __ldg(&bhh[d * GG + col]) : 0.0f);
                Cb[(size_t)row * GG + col] = acc[mf][nf][i] + bias;
            }
}

// ---------------- 4) GRU scan: 4-CTA cluster, weights SMEM-resident ----------------
// Cluster = 4 CTAs, one (dir, 16-batch chunk) per cluster. CTA rank owns hidden slice
// j in [rank*64, rank*64+64), all 3 gates: weights 3*64*256 fp32 = 196.6KB in smem.
// Full h (16 x 256) replicated in every CTA's smem (16KB). Each step: compute h_new
// for own slice, cluster.sync, broadcast slice to all 4 CTAs via st.shared::cluster,
// cluster.sync. Zero weight traffic to L2 during the scan.
#define SMEM_W_BYTES  (3 * 64 * 64 * 16)      // 196608
#define SMEM_H_BYTES  (16 * 64 * 16)          // 16384
#define SMEM_SCAN     (SMEM_W_BYTES + SMEM_H_BYTES)

__global__ void __launch_bounds__(256, 1) __cluster_dims__(4, 1, 1)
gru_scan_cl(int layer, const float* __restrict__ bhh, float* __restrict__ fin) {
    extern __shared__ char smem[];
    ulonglong2* wv  = reinterpret_cast<ulonglong2*>(smem);                    // [3][64][64]
    ulonglong2* hq  = reinterpret_cast<ulonglong2*>(smem + SMEM_W_BYTES);     // [16][64]
    float*      hqf = reinterpret_cast<float*>(hq);                           // hqf[b*256 + k]

    int tid  = threadIdx.x;
    int rank = blockIdx.x & 3;
    int cid  = blockIdx.x >> 2;
    int d    = cid & 1;
    int b0   = (cid >> 1) * 16;
    int j    = tid & 63;
    int bg   = tid >> 6;           // 4 batches per bg
    int jg   = rank * 64 + j;      // global hidden index this thread produces

    // load weight slice into smem (once)
    {
        const float4* wsrc = reinterpret_cast<const float4*>(layer ? g_WV1 : g_WV0)
                             + (size_t)(d * 4 + rank) * 12288;
        float4* wdst = reinterpret_cast<float4*>(smem);
#pragma unroll 8
        for (int i = tid; i < 12288; i += 256) wdst[i] = wsrc[i];
    }
    // zero h
    for (int i = tid; i < 16 * 256; i += 256) hqf[i] = 0.0f;
    float bn = __ldg(&bhh[d * GG + 2 * HH + jg]);   // b_hh_n[jg] (inside r*(...))

    CLUSTER_SYNC_();

    // DSMEM addresses for h column jg in each cluster CTA
    unsigned hbase = (unsigned)__cvta_generic_to_shared(hqf) + (unsigned)jg * 4u;
    unsigned haddr0 = mapa_sh(hbase, 0);
    unsigned haddr1 = mapa_sh(hbase, 1);
    unsigned haddr2 = mapa_sh(hbase, 2);
    unsigned haddr3 = mapa_sh(hbase, 3);

    float hnew[4];

    for (int s = 0; s < TT; s++) {
        int t = d ? (TT - 1 - s) : s;
        const float* gip = g_GI + ((size_t)d * (TT * BB) + (size_t)t * BB + b0 + bg * 4) * GG + jg;

        float gr[4], gz[4], gn[4];
#pragma unroll
        for (int cb = 0; cb < 4; cb++) {
            gr[cb] = __ldg(gip + (size_t)cb * GG);
            gz[cb] = __ldg(gip + (size_t)cb * GG + 256);
            gn[cb] = __ldg(gip + (size_t)cb * GG + 512);
        }

        ull ar[4] = {0, 0, 0, 0}, az[4] = {0, 0, 0, 0}, an[4] = {0, 0, 0, 0};
        const ulonglong2* hp = hq + bg * 4 * 64;

#pragma unroll 4
        for (int k4 = 0; k4 < 64; k4++) {
            ulonglong2 wr = wv[0 * 4096 + k4 * 64 + j];
            ulonglong2 wz = wv[1 * 4096 + k4 * 64 + j];
            ulonglong2 wn = wv[2 * 4096 + k4 * 64 + j];
#pragma unroll
            for (int cb = 0; cb < 4; cb++) {
                ulonglong2 h = hp[cb * 64 + k4];
                fma2(ar[cb], h.x, wr.x); fma2(ar[cb], h.y, wr.y);
                fma2(az[cb], h.x, wz.x); fma2(az[cb], h.y, wz.y);
                fma2(an[cb], h.x, wn.x); fma2(an[cb], h.y, wn.y);
            }
        }

#pragma unroll
        for (int cb = 0; cb < 4; cb++) {
            float ghr = hadd2(ar[cb]);
            float ghz = hadd2(az[cb]);
            float ghn = hadd2(an[cb]);
            float r = sigmoidf_fast(gr[cb] + ghr);
            float z = sigmoidf_fast(gz[cb] + ghz);
            float n = tanhf(gn[cb] + r * (ghn + bn));
            float hold = hqf[(bg * 4 + cb) * 256 + jg];
            hnew[cb] = n + z * (hold - n);
        }

        CLUSTER_SYNC_();   // all CTAs done reading h

        // broadcast h_new[b][jg] to all 4 CTAs' h buffers
#pragma unroll
        for (int cb = 0; cb < 4; cb++) {
            unsigned off = (unsigned)(bg * 4 + cb) * 1024u;
            asm volatile("st.shared::cluster.f32 [%0], %1;" :: "r"(haddr0 + off), "f"(hnew[cb]) : "memory");
            asm volatile("st.shared::cluster.f32 [%0], %1;" :: "r"(haddr1 + off), "f"(hnew[cb]) : "memory");
            asm volatile("st.shared::cluster.f32 [%0], %1;" :: "r"(haddr2 + off), "f"(hnew[cb]) : "memory");
            asm volatile("st.shared::cluster.f32 [%0], %1;" :: "r"(haddr3 + off), "f"(hnew[cb]) : "memory");
        }

        if (layer == 0) {
            float* hpout = g_H1 + ((size_t)t * BB + b0 + bg * 4) * (2 * HH) + (size_t)d * HH + jg;
#pragma unroll
            for (int cb = 0; cb < 4; cb++) hpout[(size_t)cb * 2 * HH] = hnew[cb];
        }

        CLUSTER_SYNC_();   // h_new visible everywhere
    }

    if (layer != 0) {
#pragma unroll
        for (int cb = 0; cb < 4; cb++)
            fin[(size_t)(b0 + bg * 4 + cb) * (2 * HH) + (size_t)d * HH + jg] = hnew[cb];
    }
}

// ---------------- launch ----------------
extern "C" void kernel_launch(void* const* d_in, const int* in_sizes, int n_in,
                              void* d_out, int out_size) {
    (void)in_sizes; (void)n_in; (void)out_size;
    const float* x     = (const float*)d_in[0];
    const float* w_ih0 = (const float*)d_in[1];
    const float* w_hh0 = (const float*)d_in[2];
    const float* b_ih0 = (const float*)d_in[3];
    const float* b_hh0 = (const float*)d_in[4];
    const float* w_ih1 = (const float*)d_in[5];
    const float* w_hh1 = (const float*)d_in[6];
    const float* b_ih1 = (const float*)d_in[7];
    const float* b_hh1 = (const float*)d_in[8];
    float* out = (float*)d_out;

    cudaFuncSetAttribute(gru_scan_cl, cudaFuncAttributeMaxDynamicSharedMemorySize, SMEM_SCAN);

    transpose_x<<<(BB * TT * (DD / 4) + 255) / 256, 256>>>(x);
    prep_whh<<<(2 * 4 * 3 * 64 * 64 + 255) / 256, 256>>>(0, w_hh0);
    prep_whh<<<(2 * 4 * 3 * 64 * 64 + 255) / 256, 256>>>(1, w_hh1);

    dim3 gg(512, 6, 2);   // M/128, 768/128, dirs
    gemm_tf32<<<gg, 256>>>(0, w_ih0, b_ih0, b_hh0);
    gru_scan_cl<<<128, 256, SMEM_SCAN>>>(0, b_hh0, nullptr);
    gemm_tf32<<<gg, 256>>>(1, w_ih1, b_ih1, b_hh1);
    gru_scan_cl<<<128, 256, SMEM_SCAN>>>(1, b_hh1, out);
}